// round 10
// baseline (speedup 1.0000x reference)
#include <cuda_runtime.h>
#include <cuda_fp16.h>
#include <cstdint>

// ============================================================================
// out[z,k] = sum_{i,j} M[k,i,j] * f1[z,i] * f2[z,j]
// Dense fp16 warp-MMA GEMM (fp32 accum):  out = P @ W
//   P[z, i*32+j] = f1[z,i]*f2[z,j]  (HMUL2 of pre-converted fp16 operands)
//   W[i*32+j, k] = M[k,i,j]         (pre-packed fp16x2 fragment order, RN)
//
// R10: occupancy push. Warp tile m32 x n16, 128-thread CTAs (Z_CTA=32,
//   4 n-quarter warps), <=64 regs -> __launch_bounds__(128,8): 32 warps/SM.
//   Chip B traffic per MMA unchanged (4B/MMA); HMUL2/MMA doubles (fma has
//   headroom). Per-warp LDG B stream, 1-chunk lookahead (cp.async was neutral).
// ============================================================================

#define N_I 32
#define N_J 32
#define N_K 64
#define Z_CTA 32               // one m32 group
#define NTHREADS 128           // 4 warps = 4 n-quarters
#define N_CHUNKS 64            // K = 1024 / 16

// Packed W (uint32 = fp16x2):
//   offset = chunk*512 + nq*128 + lane*4 + slot ; slot = ntl*2 + breg
//   n = nq*16 + ntl*8 + qr ; i = chunk/2 ; j0 = (chunk&1)*16 + 2c + 8*breg
//   value = {f16rn(M[n,i,j0]), f16rn(M[n,i,j0+1])}   (qr=lane/4, c=lane%4)
// +1 zero pad chunk so the last prefetch is legal.
__device__ uint32_t g_Wp[(N_CHUNKS + 1) * 512];   // 133 KB

// ---------------------------------------------------------------------------
__global__ void etp_pack_kernel(const float* __restrict__ Mx) {
    int idx = blockIdx.x * blockDim.x + threadIdx.x;   // 0..33279
    if (idx >= N_CHUNKS * 512) {
        if (idx < (N_CHUNKS + 1) * 512) g_Wp[idx] = 0u;
        return;
    }
    int chunk = idx >> 9;
    int rem   = idx & 511;
    int nq    = rem >> 7;
    int r3    = rem & 127;
    int lane  = r3 >> 2;
    int slot  = r3 & 3;
    int ntl   = slot >> 1;
    int breg  = slot & 1;
    int qr    = lane >> 2;
    int c     = lane & 3;
    int n     = nq * 16 + ntl * 8 + qr;
    int i     = chunk >> 1;
    int j0    = ((chunk & 1) << 4) + 2 * c + 8 * breg;
    float v0 = Mx[n * (N_I * N_J) + i * N_J + j0];
    float v1 = Mx[n * (N_I * N_J) + i * N_J + j0 + 1];
    __half2 h = __floats2half2_rn(v0, v1);             // lo=v0, hi=v1
    g_Wp[idx] = *reinterpret_cast<uint32_t*>(&h);
}

// ---------------------------------------------------------------------------

#define HMUL2(d, x, y) \
    asm("mul.rn.f16x2 %0, %1, %2;" : "=r"(d) : "r"(x), "r"(y))

#define MMA_F16(cacc, a0, a1, a2, a3, b0, b1)                                 \
    asm volatile(                                                             \
        "mma.sync.aligned.m16n8k16.row.col.f32.f16.f16.f32 "                  \
        "{%0,%1,%2,%3}, {%4,%5,%6,%7}, {%8,%9}, {%0,%1,%2,%3};"               \
        : "+f"((cacc)[0]), "+f"((cacc)[1]), "+f"((cacc)[2]), "+f"((cacc)[3])  \
        : "r"(a0), "r"(a1), "r"(a2), "r"(a3), "r"(b0), "r"(b1))

__global__ void __launch_bounds__(NTHREADS, 8)
etp_mma_kernel(const float* __restrict__ F1,
               const float* __restrict__ F2,
               float* __restrict__ Out) {
    // f1 broadcast half2(v,v), stride 32, XOR-swizzled:
    //   word = row*32 + (col ^ ((row&7)<<2))
    __shared__ uint32_t f1h[Z_CTA * 32];                 // 4 KB

    const int tid  = threadIdx.x;
    const int nq   = tid >> 5;           // warp = n-quarter 0..3
    const int lane = tid & 31;
    const int qr   = lane >> 2;          // 0..7
    const int c    = lane & 3;           // 0..3

    const size_t zbase = (size_t)blockIdx.x * Z_CTA;

    // ---- stage f1 (broadcast half2, swizzled): 256 float4, 2 per thread ----
    {
        const float4* f1g = reinterpret_cast<const float4*>(F1 + zbase * N_I);
#pragma unroll
        for (int t = 0; t < 2; t++) {
            int i4 = tid + t * NTHREADS;          // 0..255
            int row = i4 >> 3, cg = i4 & 7;
            float4 v1 = __ldg(f1g + i4);
            __half2 h0 = __half2half2(__float2half_rn(v1.x));
            __half2 h1 = __half2half2(__float2half_rn(v1.y));
            __half2 h2 = __half2half2(__float2half_rn(v1.z));
            __half2 h3 = __half2half2(__float2half_rn(v1.w));
            uint4 pk;
            pk.x = *reinterpret_cast<uint32_t*>(&h0);
            pk.y = *reinterpret_cast<uint32_t*>(&h1);
            pk.z = *reinterpret_cast<uint32_t*>(&h2);
            pk.w = *reinterpret_cast<uint32_t*>(&h3);
            int col = (cg * 4) ^ ((row & 7) << 2);       // keeps low 2 bits
            *reinterpret_cast<uint4*>(&f1h[row * 32 + col]) = pk;
        }
    }

    // ---- f2 pair regs direct from gmem: s2 = jh*2+breg -> j0 = jh*16+breg*8+2c
    uint32_t f2h[4][4];
#pragma unroll
    for (int rr = 0; rr < 4; rr++) {
        const float* fr = F2 + (zbase + qr + rr * 8) * N_J;
#pragma unroll
        for (int s2 = 0; s2 < 4; s2++) {
            int jh = s2 >> 1, breg = s2 & 1;
            int j0 = jh * 16 + breg * 8 + 2 * c;
            float2 v = *reinterpret_cast<const float2*>(fr + j0);
            __half2 h = __floats2half2_rn(v.x, v.y);
            f2h[rr][s2] = *reinterpret_cast<uint32_t*>(&h);
        }
    }

    float C[2][2][4];                    // [mtile][ntile][quad]
#pragma unroll
    for (int mt = 0; mt < 2; mt++)
#pragma unroll
        for (int nt = 0; nt < 2; nt++)
#pragma unroll
            for (int q = 0; q < 4; q++) C[mt][nt][q] = 0.0f;

    __syncthreads();                     // f1h visible

    const int sw = qr << 2;              // f1 swizzle term (row&7 == qr)

    // ---- B stream: 1 lane-contiguous LDG.128 per chunk, 1-chunk lookahead
    const uint4* wq = reinterpret_cast<const uint4*>(g_Wp) + nq * 32 + lane;
    uint4 bA = __ldg(wq);

#pragma unroll 1
    for (int ig = 0; ig < N_I; ig++) {
        uint32_t f1v[4];
#pragma unroll
        for (int rr = 0; rr < 4; rr++)
            f1v[rr] = f1h[(qr + rr * 8) * 32 + (ig ^ sw)];

#pragma unroll
        for (int jh = 0; jh < 2; jh++) {
            const uint4 b0 = bA;

            wq += 128;                   // next chunk (pad keeps last legal)
            bA = __ldg(wq);

            // A fragments: one HMUL2 each
            uint32_t a[2][4];
#pragma unroll
            for (int mt = 0; mt < 2; mt++) {
                HMUL2(a[mt][0], f1v[2 * mt],     f2h[2 * mt][jh * 2 + 0]);
                HMUL2(a[mt][1], f1v[2 * mt + 1], f2h[2 * mt + 1][jh * 2 + 0]);
                HMUL2(a[mt][2], f1v[2 * mt],     f2h[2 * mt][jh * 2 + 1]);
                HMUL2(a[mt][3], f1v[2 * mt + 1], f2h[2 * mt + 1][jh * 2 + 1]);
            }

            // 4 MMAs (2 mtiles x 2 ntiles), K=16 each
#pragma unroll
            for (int mt = 0; mt < 2; mt++) {
                MMA_F16(C[mt][0], a[mt][0], a[mt][1], a[mt][2], a[mt][3], b0.x, b0.y);
                MMA_F16(C[mt][1], a[mt][0], a[mt][1], a[mt][2], a[mt][3], b0.z, b0.w);
            }
        }
    }

    // ---- epilogue ----
#pragma unroll
    for (int mt = 0; mt < 2; mt++) {
        const size_t z0 = zbase + qr + mt * 16;
        const size_t z1 = z0 + 8;
#pragma unroll
        for (int nt = 0; nt < 2; nt++) {
            const int col = nq * 16 + nt * 8 + 2 * c;
            *reinterpret_cast<float2*>(Out + z0 * N_K + col) =
                make_float2(C[mt][nt][0], C[mt][nt][1]);
            *reinterpret_cast<float2*>(Out + z1 * N_K + col) =
                make_float2(C[mt][nt][2], C[mt][nt][3]);
        }
    }
}

// ---------------------------------------------------------------------------

extern "C" void kernel_launch(void* const* d_in, const int* in_sizes, int n_in,
                              void* d_out, int out_size) {
    const float* f1 = (const float*)d_in[0];   // [Z, 32]
    const float* f2 = (const float*)d_in[1];   // [Z, 32]
    const float* mx = (const float*)d_in[2];   // [64, 32, 32]
    float* out = (float*)d_out;                // [Z, 64]

    const int z_total = in_sizes[0] / N_I;     // 131072
    const int blocks = z_total / Z_CTA;        // 4096

    etp_pack_kernel<<<130, 256>>>(mx);         // 130*256 = 33280 incl. pad
    etp_mma_kernel<<<blocks, NTHREADS>>>(f1, f2, out);
}

// round 11
// speedup vs baseline: 1.0420x; 1.0420x over previous
#include <cuda_runtime.h>
#include <cuda_fp16.h>
#include <cstdint>

// ============================================================================
// out[z,k] = sum_{i,j} M[k,i,j] * f1[z,i] * f2[z,j]
// Dense fp16 warp-MMA GEMM (fp32 accum):  out = P @ W
//   P[z, i*32+j] = f1[z,i]*f2[z,j]  (HMUL2 of pre-converted fp16 operands)
//   W[i*32+j, k] = M[k,i,j]         (pre-packed fp16x2 fragment order, RN)
//
// R11 = R8 (best: m32n32 warp tile, 256thr, 3 CTA/SM) +
//   - f1 staged TRANSPOSED as [i][mgroup][qr][rr] -> the 4 per-chunk f1
//     values are one LDS.128 (was 4x LDS.32)
//   - f1 double-buffered one chunk ahead -> LDS latency fully covered
// ============================================================================

#define N_I 32
#define N_J 32
#define N_K 64
#define Z_CTA 128              // 4 m-groups x 32 rows
#define NTHREADS 256           // 8 warps = 4 m-groups x 2 n-halves
#define N_CHUNKS 64            // K = 1024 / 16

// Packed W (uint32 = fp16x2), layout validated in R7/R8:
//   offset = chunk*512 + nhalf*256 + pair*128 + lane*4 + slot
//   slot = ntl*2 + breg ; n = nhalf*32 + (pair*2+ntl)*8 + qr
//   i = chunk/2 ; j0 = (chunk&1)*16 + 2c + 8*breg ; value = {f16(j0), f16(j0+1)}
// +1 zero pad chunk so the last prefetch is legal.
__device__ uint32_t g_Wp[(N_CHUNKS + 1) * 512];   // 133 KB

// ---------------------------------------------------------------------------
__global__ void etp_pack_kernel(const float* __restrict__ Mx) {
    int idx = blockIdx.x * blockDim.x + threadIdx.x;   // 0..33279
    if (idx >= N_CHUNKS * 512) {
        if (idx < (N_CHUNKS + 1) * 512) g_Wp[idx] = 0u;
        return;
    }
    int chunk = idx >> 9;
    int rem   = idx & 511;
    int nhalf = rem >> 8;
    int r2    = rem & 255;
    int pair  = r2 >> 7;
    int r3    = r2 & 127;
    int lane  = r3 >> 2;
    int slot  = r3 & 3;
    int ntl   = slot >> 1;
    int breg  = slot & 1;
    int qr    = lane >> 2;
    int c     = lane & 3;
    int n     = nhalf * 32 + (pair * 2 + ntl) * 8 + qr;
    int i     = chunk >> 1;
    int j0    = ((chunk & 1) << 4) + 2 * c + 8 * breg;
    float v0 = Mx[n * (N_I * N_J) + i * N_J + j0];
    float v1 = Mx[n * (N_I * N_J) + i * N_J + j0 + 1];
    __half2 h = __floats2half2_rn(v0, v1);             // lo=v0, hi=v1
    g_Wp[idx] = *reinterpret_cast<uint32_t*>(&h);
}

// ---------------------------------------------------------------------------

#define HMUL2(d, x, y) \
    asm("mul.rn.f16x2 %0, %1, %2;" : "=r"(d) : "r"(x), "r"(y))

#define MMA_F16(cacc, a0, a1, a2, a3, b0, b1)                                 \
    asm volatile(                                                             \
        "mma.sync.aligned.m16n8k16.row.col.f32.f16.f16.f32 "                  \
        "{%0,%1,%2,%3}, {%4,%5,%6,%7}, {%8,%9}, {%0,%1,%2,%3};"               \
        : "+f"((cacc)[0]), "+f"((cacc)[1]), "+f"((cacc)[2]), "+f"((cacc)[3])  \
        : "r"(a0), "r"(a1), "r"(a2), "r"(a3), "r"(b0), "r"(b1))

__global__ void __launch_bounds__(NTHREADS, 3)
etp_mma_kernel(const float* __restrict__ F1,
               const float* __restrict__ F2,
               float* __restrict__ Out) {
    // f1 transposed: uint4 index = ig*32 + mgroup*8 + qr ; components = rr 0..3
    // value = broadcast half2(f1[row, ig]) with row = mgroup*32 + rr*8 + qr
    // (+1 ig row of pad so the last prefetch is legal)
    __shared__ uint4 f1T[(N_I + 1) * 32];                // 16.5 KB

    const int tid    = threadIdx.x;
    const int warp   = tid >> 5;
    const int lane   = tid & 31;
    const int mgroup = warp >> 1;        // 0..3, 32 rows each
    const int nhalf  = warp & 1;         // n columns [nhalf*32, +32)
    const int qr     = lane >> 2;        // 0..7
    const int c      = lane & 3;         // 0..3

    const size_t zbase = (size_t)blockIdx.x * Z_CTA;

    // ---- stage f1 transposed (broadcast half2) ----
    {
        const float4* f1g = reinterpret_cast<const float4*>(F1 + zbase * N_I);
        uint32_t* f1w = reinterpret_cast<uint32_t*>(f1T);
#pragma unroll
        for (int t = 0; t < 4; t++) {
            int i4 = tid + t * NTHREADS;          // 0..1023
            int row = i4 >> 3, cg = i4 & 7;
            float4 v = __ldg(f1g + i4);
            float vv[4] = {v.x, v.y, v.z, v.w};
            const int base = (row >> 5) * 8 + (row & 7);   // mgroup*8 + qr
            const int rr   = (row >> 3) & 3;
#pragma unroll
            for (int g = 0; g < 4; g++) {
                __half2 h = __half2half2(__float2half_rn(vv[g]));
                int ig = cg * 4 + g;
                f1w[(ig * 32 + base) * 4 + rr] = *reinterpret_cast<uint32_t*>(&h);
            }
        }
    }

    // ---- f2 pair regs direct from gmem: s2 = jh*2+breg -> j0 = jh*16+breg*8+2c
    uint32_t f2h[4][4];
#pragma unroll
    for (int rr = 0; rr < 4; rr++) {
        const float* fr = F2 + (zbase + mgroup * 32 + qr + rr * 8) * N_J;
#pragma unroll
        for (int s2 = 0; s2 < 4; s2++) {
            int jh = s2 >> 1, breg = s2 & 1;
            int j0 = jh * 16 + breg * 8 + 2 * c;
            float2 v = *reinterpret_cast<const float2*>(fr + j0);
            __half2 h = __floats2half2_rn(v.x, v.y);
            f2h[rr][s2] = *reinterpret_cast<uint32_t*>(&h);
        }
    }

    float C[2][4][4];                    // [mtile][ntile][quad]
#pragma unroll
    for (int mt = 0; mt < 2; mt++)
#pragma unroll
        for (int nt = 0; nt < 4; nt++)
#pragma unroll
            for (int q = 0; q < 4; q++) C[mt][nt][q] = 0.0f;

    __syncthreads();                     // f1T visible

    // ---- B stream: 2x lane-contiguous LDG.128 per chunk, 1-chunk lookahead
    const uint4* wq = reinterpret_cast<const uint4*>(g_Wp)
                      + nhalf * 64 + lane;
    uint4 bA = __ldg(wq);                // pair 0: n-tiles 0,1
    uint4 bB = __ldg(wq + 32);           // pair 1: n-tiles 2,3

    // ---- f1 stream: one LDS.128 per ig, double-buffered ----
    const uint4* f1p = f1T + mgroup * 8 + qr;
    uint4 f1cur = f1p[0];

#pragma unroll 1
    for (int ig = 0; ig < N_I; ig++) {
        const uint4 f1nxt = f1p[(ig + 1) * 32];   // covered by this chunk's work

#pragma unroll
        for (int jh = 0; jh < 2; jh++) {
            const uint4 b0 = bA, b1 = bB;

            wq += 128;                   // next chunk (pad keeps last legal)
            bA = __ldg(wq);
            bB = __ldg(wq + 32);

            // A fragments: one HMUL2 each (f1cur comps: x,y = mt0; z,w = mt1)
            uint32_t a[2][4];
            HMUL2(a[0][0], f1cur.x, f2h[0][jh * 2 + 0]);
            HMUL2(a[0][1], f1cur.y, f2h[1][jh * 2 + 0]);
            HMUL2(a[0][2], f1cur.x, f2h[0][jh * 2 + 1]);
            HMUL2(a[0][3], f1cur.y, f2h[1][jh * 2 + 1]);
            HMUL2(a[1][0], f1cur.z, f2h[2][jh * 2 + 0]);
            HMUL2(a[1][1], f1cur.w, f2h[3][jh * 2 + 0]);
            HMUL2(a[1][2], f1cur.z, f2h[2][jh * 2 + 1]);
            HMUL2(a[1][3], f1cur.w, f2h[3][jh * 2 + 1]);

            // 8 MMAs (2 mtiles x 4 ntiles), K=16 each
#pragma unroll
            for (int mt = 0; mt < 2; mt++) {
                MMA_F16(C[mt][0], a[mt][0], a[mt][1], a[mt][2], a[mt][3], b0.x, b0.y);
                MMA_F16(C[mt][1], a[mt][0], a[mt][1], a[mt][2], a[mt][3], b0.z, b0.w);
                MMA_F16(C[mt][2], a[mt][0], a[mt][1], a[mt][2], a[mt][3], b1.x, b1.y);
                MMA_F16(C[mt][3], a[mt][0], a[mt][1], a[mt][2], a[mt][3], b1.z, b1.w);
            }
        }

        f1cur = f1nxt;
    }

    // ---- epilogue ----
    const int r0 = mgroup * 32 + qr;
#pragma unroll
    for (int mt = 0; mt < 2; mt++) {
        const size_t z0 = zbase + r0 + mt * 16;
        const size_t z1 = z0 + 8;
#pragma unroll
        for (int nt = 0; nt < 4; nt++) {
            const int col = nhalf * 32 + nt * 8 + 2 * c;
            *reinterpret_cast<float2*>(Out + z0 * N_K + col) =
                make_float2(C[mt][nt][0], C[mt][nt][1]);
            *reinterpret_cast<float2*>(Out + z1 * N_K + col) =
                make_float2(C[mt][nt][2], C[mt][nt][3]);
        }
    }
}

// ---------------------------------------------------------------------------

extern "C" void kernel_launch(void* const* d_in, const int* in_sizes, int n_in,
                              void* d_out, int out_size) {
    const float* f1 = (const float*)d_in[0];   // [Z, 32]
    const float* f2 = (const float*)d_in[1];   // [Z, 32]
    const float* mx = (const float*)d_in[2];   // [64, 32, 32]
    float* out = (float*)d_out;                // [Z, 64]

    const int z_total = in_sizes[0] / N_I;     // 131072
    const int blocks = z_total / Z_CTA;        // 1024

    etp_pack_kernel<<<130, 256>>>(mx);         // 130*256 = 33280 incl. pad
    etp_mma_kernel<<<blocks, NTHREADS>>>(f1, f2, out);
}